// round 12
// baseline (speedup 1.0000x reference)
#include <cuda_runtime.h>
#include <cuda_bf16.h>

#define L_  1024
#define DM  1024
#define DI  2048
#define NS  16
#define DR  64
#define BB  2
#define CH  8
#define CT  (L_/CH)                 // 128 steps per chunk

typedef unsigned int        u32;
typedef unsigned short      u16;
typedef unsigned long long  u64;

// ---------------- scratch (static device globals; no allocation) -------------
__device__ float g_hid_t [BB*DI*L_];   // hidden, (b, d, t)
__device__ float g_gate_t[BB*DI*L_];   // gate,   (b, d, t)
__device__ float g_ssm   [BB*L_*96];   // (b*t, 96): [0:64)=dt_pre, [64:80)=B, [80:96)=C
__device__ float g_dt_t  [BB*DI*L_];   // softplus(dt), (b, d, t)
__device__ u16   g_x_hi  [BB*L_*DM];   // bf16 hi/lo splits, row-major (m, k)
__device__ u16   g_x_lo  [BB*L_*DM];
__device__ u16   g_win_hi[2*DI*DM];
__device__ u16   g_win_lo[2*DI*DM];
__device__ u16   g_wout_hi[DM*DI];
__device__ u16   g_wout_lo[DM*DI];
__device__ u32   g_so_pk [BB*L_*DI];   // scan output packed (hi|lo<<16), (b, t, d)
__device__ u16   g_so_hi [BB*L_*DI];   // split views for the GEMM
__device__ u16   g_so_lo [BB*L_*DI];

__device__ __forceinline__ float softplusf(float x) {
    return x > 20.f ? x : log1pf(__expf(x));
}
__device__ __forceinline__ void split2(float v, u16& h, u16& l) {
    __nv_bfloat16 bh = __float2bfloat16_rn(v);
    float hf = __bfloat162float(bh);
    __nv_bfloat16 bl = __float2bfloat16_rn(v - hf);
    h = __bfloat16_as_ushort(bh);
    l = __bfloat16_as_ushort(bl);
}
__device__ __forceinline__ u32 pack_split(float v) {
    u16 h, l; split2(v, h, l);
    return (u32)h | ((u32)l << 16);
}
__device__ __forceinline__ u32 smem_u32(const void* p) {
    u32 a;
    asm("{ .reg .u64 t; cvta.to.shared.u64 t, %1; cvt.u32.u64 %0, t; }" : "=r"(a) : "l"(p));
    return a;
}
__device__ __forceinline__ void ldm_x4(u32& r0, u32& r1, u32& r2, u32& r3, u32 addr) {
    asm volatile("ldmatrix.sync.aligned.m8n8.x4.shared.b16 {%0,%1,%2,%3}, [%4];"
                 : "=r"(r0), "=r"(r1), "=r"(r2), "=r"(r3) : "r"(addr));
}
__device__ __forceinline__ void mma_bf16(float* c, const u32* a, u32 b0, u32 b1) {
    asm volatile("mma.sync.aligned.m16n8k16.row.col.f32.bf16.bf16.f32 "
                 "{%0,%1,%2,%3}, {%4,%5,%6,%7}, {%8,%9}, {%0,%1,%2,%3};"
                 : "+f"(c[0]), "+f"(c[1]), "+f"(c[2]), "+f"(c[3])
                 : "r"(a[0]), "r"(a[1]), "r"(a[2]), "r"(a[3]), "r"(b0), "r"(b1));
}
__device__ __forceinline__ void cp16(u32 dst, const void* src) {
    asm volatile("cp.async.cg.shared.global [%0], [%1], 16;" :: "r"(dst), "l"(src));
}
__device__ __forceinline__ void cp_commit() {
    asm volatile("cp.async.commit_group;" ::: "memory");
}
template<int N>
__device__ __forceinline__ void cp_wait() {
    asm volatile("cp.async.wait_group %0;" :: "n"(N) : "memory");
}

// =============================================================================
//  bf16x3 split GEMM on mma.sync.  C = Ah*Bh + Ah*Bl + Al*Bh (fp32 acc).
//  CTA tile TM=128 x TN (128 in_proj / 64 out_proj), BK=16, 4-stage cp.async
//  ring, ONE __syncthreads per k-step.  8 warps: wm=wid>>1 (m 32), wn=wid&1
//  (n TN/2).  Stage rows padded to 48B (conflict-free ldmatrix phases).
// =============================================================================

// EPI 0: in_proj (A=x, B=w_in) -> transposed split write hid/gate (b,d,t)
// EPI 1: out_proj (A=so, B=w_out) -> row-major Out
template<int EPI>
__global__ void __launch_bounds__(256, 2) gemm_mma(int Kfull, float* __restrict__ Out)
{
    constexpr int TM    = 128;
    constexpr int TN    = (EPI == 0) ? 128 : 64;
    constexpr int NJ    = TN / 32;          // B 16-col tiles per warp
    constexpr int MATA  = TM * 48;
    constexpr int MATB2 = TN * 48;
    constexpr int BOFF  = 2 * MATA;
    constexpr int STAGE = 2 * MATA + 2 * MATB2;
    constexpr int CPT   = (2 * TM + 2 * TN) * 2 / 256;  // cp16 per thread per stage
    constexpr int CSLD  = TN + 4;

    const u16* Ahp = (EPI == 0) ? g_x_hi   : g_so_hi;
    const u16* Alp = (EPI == 0) ? g_x_lo   : g_so_lo;
    const u16* Bhp = (EPI == 0) ? g_win_hi : g_wout_hi;
    const u16* Blp = (EPI == 0) ? g_win_lo : g_wout_lo;

    extern __shared__ __align__(16) char sm[];
    u32 smb = smem_u32(sm);

    int tid = threadIdx.x;
    int lane = tid & 31, wid = tid >> 5;
    int wm = wid >> 1, wn = wid & 1;
    int n0 = blockIdx.x * TN;
    int m0 = blockIdx.y * TM;

    float acc[2][NJ * 2][4] = {};
    const int nch = Kfull / 16;

    auto issue_stage = [&](int buf, int k0) {
        u32 dstb = smb + buf * STAGE;
        #pragma unroll
        for (int r = 0; r < CPT; r++) {
            int li = tid + r * 256;
            int half = li & 1;
            int v = li >> 1;
            const u16* s; u32 mo; int row; int rb;
            if (v < TM)               { s = Ahp; mo = 0;            row = v;            rb = m0; }
            else if (v < 2*TM)        { s = Alp; mo = MATA;         row = v - TM;       rb = m0; }
            else if (v < 2*TM + TN)   { s = Bhp; mo = BOFF;         row = v - 2*TM;     rb = n0; }
            else                      { s = Blp; mo = BOFF + MATB2; row = v - 2*TM - TN; rb = n0; }
            cp16(dstb + mo + (u32)(row * 48 + half * 16),
                 s + (size_t)(rb + row) * Kfull + k0 + half * 8);
        }
    };

    issue_stage(0, 0);  cp_commit();
    issue_stage(1, 16); cp_commit();
    issue_stage(2, 32); cp_commit();

    int rl = lane & 15;
    int kc = (lane >> 4) * 16;     // k-half byte offset

    for (int i = 0; i < nch; i++) {
        int rem = nch - 1 - i;
        if (rem >= 2)      cp_wait<2>();
        else if (rem == 1) cp_wait<1>();
        else               cp_wait<0>();
        __syncthreads();
        if (i + 3 < nch) { issue_stage((i + 3) & 3, (i + 3) * 16); cp_commit(); }

        u32 sb = smb + (i & 3) * STAGE;
        u32 ah[2][4], al[2][4];
        #pragma unroll
        for (int mi = 0; mi < 2; mi++) {
            u32 a = sb + (u32)((wm * 32 + mi * 16 + rl) * 48 + kc);
            ldm_x4(ah[mi][0], ah[mi][1], ah[mi][2], ah[mi][3], a);
            ldm_x4(al[mi][0], al[mi][1], al[mi][2], al[mi][3], a + MATA);
        }
        #pragma unroll
        for (int nj2 = 0; nj2 < NJ; nj2++) {
            u32 a = sb + BOFF + (u32)((wn * (TN / 2) + nj2 * 16 + rl) * 48 + kc);
            u32 bh[4], bl[4];
            ldm_x4(bh[0], bh[1], bh[2], bh[3], a);
            ldm_x4(bl[0], bl[1], bl[2], bl[3], a + MATB2);
            // term-major: same accumulator reused only every 4 MMAs
            #pragma unroll
            for (int mi = 0; mi < 2; mi++)
                #pragma unroll
                for (int o = 0; o < 2; o++)
                    mma_bf16(acc[mi][nj2 * 2 + o], ah[mi], bh[o], bh[o + 2]);
            #pragma unroll
            for (int mi = 0; mi < 2; mi++)
                #pragma unroll
                for (int o = 0; o < 2; o++)
                    mma_bf16(acc[mi][nj2 * 2 + o], ah[mi], bl[o], bl[o + 2]);
            #pragma unroll
            for (int mi = 0; mi < 2; mi++)
                #pragma unroll
                for (int o = 0; o < 2; o++)
                    mma_bf16(acc[mi][nj2 * 2 + o], al[mi], bh[o], bh[o + 2]);
        }
    }
    __syncthreads();

    // ---- epilogue: stage C (TM x CSLD fp32) in smem, coalesced write-out ----
    float* Cs = (float*)sm;
    {
        int tq = lane >> 2, tr2 = (lane & 3) * 2;
        #pragma unroll
        for (int mi = 0; mi < 2; mi++) {
            #pragma unroll
            for (int nj = 0; nj < NJ * 2; nj++) {
                int row = wm * 32 + mi * 16 + tq;
                int col = wn * (TN / 2) + nj * 8 + tr2;
                float* c = acc[mi][nj];
                *(float2*)&Cs[row * CSLD + col]       = make_float2(c[0], c[1]);
                *(float2*)&Cs[(row + 8) * CSLD + col] = make_float2(c[2], c[3]);
            }
        }
    }
    __syncthreads();

    if (EPI == 0) {
        int bb = m0 >> 10;
        int t0 = m0 & 1023;
        float* dst = (n0 < DI) ? g_hid_t : g_gate_t;
        int nb = n0 & (DI - 1);
        #pragma unroll
        for (int r = 0; r < 16; r++) {
            int li = tid + r * 256;
            int col = li & 127, mb = li >> 7;
            float4 v = make_float4(Cs[(mb * 4 + 0) * CSLD + col],
                                   Cs[(mb * 4 + 1) * CSLD + col],
                                   Cs[(mb * 4 + 2) * CSLD + col],
                                   Cs[(mb * 4 + 3) * CSLD + col]);
            *(float4*)&dst[((size_t)bb * DI + nb + col) * L_ + t0 + mb * 4] = v;
        }
    } else {
        #pragma unroll
        for (int r = 0; r < 8; r++) {
            int li = tid + r * 256;
            int row = li >> 4, cb = li & 15;
            float4 v = *(float4*)&Cs[row * CSLD + cb * 4];
            *(float4*)&Out[(size_t)(m0 + row) * DM + n0 + cb * 4] = v;
        }
    }
}

// ---------------- fp32 -> split bf16 hi/lo converter -------------------------
template<int DST>
__global__ void cvt_pack(const float* __restrict__ in, int n4)
{
    u16* oh = (DST == 0) ? g_x_hi : (DST == 1) ? g_win_hi : g_wout_hi;
    u16* ol = (DST == 0) ? g_x_lo : (DST == 1) ? g_win_lo : g_wout_lo;
    int i = blockIdx.x * blockDim.x + threadIdx.x;
    if (i < n4) {
        float4 v = ((const float4*)in)[i];
        ushort4 h, l;
        split2(v.x, h.x, l.x); split2(v.y, h.y, l.y);
        split2(v.z, h.z, l.z); split2(v.w, h.w, l.w);
        ((ushort4*)oh)[i] = h;
        ((ushort4*)ol)[i] = l;
    }
}

// packed so -> split hi/lo (fully coalesced)
__global__ void cvt_so(int n4)
{
    int i = blockIdx.x * blockDim.x + threadIdx.x;
    if (i < n4) {
        uint4 p = ((const uint4*)g_so_pk)[i];
        ushort4 h = make_ushort4((u16)(p.x & 0xffff), (u16)(p.y & 0xffff),
                                 (u16)(p.z & 0xffff), (u16)(p.w & 0xffff));
        ushort4 l = make_ushort4((u16)(p.x >> 16), (u16)(p.y >> 16),
                                 (u16)(p.z >> 16), (u16)(p.w >> 16));
        ((ushort4*)g_so_hi)[i] = h;
        ((ushort4*)g_so_lo)[i] = l;
    }
}

// =============================================================================
//  Small GEMM (64x64, 4x4 micro) for x_proj / dt_proj  (FFMA)
// =============================================================================
template<int EPI, bool AKMAJ, int ASRC>
__global__ __launch_bounds__(256)
void gemm_k(const float* __restrict__ W, int M, int N, int K, int lda,
            const float* __restrict__ bias)
{
    const float* A = (ASRC == 1) ? g_hid_t : g_ssm;

    __shared__ __align__(16) float As[16][68];
    __shared__ __align__(16) float Bs[16][68];

    int tid = threadIdx.x;
    int n0 = blockIdx.x * 64;
    int m0 = blockIdx.y * 64;
    int tr = tid >> 4;
    int tc = tid & 15;
    float acc[4][4] = {};

    for (int k0 = 0; k0 < K; k0 += 16) {
        if (AKMAJ) {
            #pragma unroll
            for (int i = 0; i < 4; i++) {
                int li = tid + i * 256;
                int m = li & 63, k = li >> 6;
                int gm = m0 + m;
                As[k][m] = A[(((gm >> 10) * K) + k0 + k) * L_ + (gm & 1023)];
            }
        } else {
            #pragma unroll
            for (int i = 0; i < 4; i++) {
                int li = tid + i * 256;
                int k = li & 15, m = li >> 4;
                As[k][m] = A[(m0 + m) * lda + k0 + k];
            }
        }
        #pragma unroll
        for (int i = 0; i < 4; i++) {
            int li = tid + i * 256;
            int k = li & 15, n = li >> 4;
            int gn = n0 + n;
            Bs[k][n] = (gn < N) ? W[gn * K + k0 + k] : 0.f;
        }
        __syncthreads();
        #pragma unroll
        for (int k = 0; k < 16; k++) {
            float4 av = *(const float4*)&As[k][tr * 4];
            float4 bv = *(const float4*)&Bs[k][tc * 4];
            float a4[4] = {av.x, av.y, av.z, av.w};
            float b4[4] = {bv.x, bv.y, bv.z, bv.w};
            #pragma unroll
            for (int i = 0; i < 4; i++)
                #pragma unroll
                for (int j = 0; j < 4; j++)
                    acc[i][j] = fmaf(a4[i], b4[j], acc[i][j]);
        }
        __syncthreads();
    }

    if (EPI == 1) {
        #pragma unroll
        for (int i = 0; i < 4; i++) {
            int gm = m0 + tr * 4 + i;
            #pragma unroll
            for (int j = 0; j < 4; j++) {
                int gn = n0 + tc * 4 + j;
                if (gn < N) g_ssm[gm * 96 + gn] = acc[i][j];
            }
        }
    } else {
        int bb = m0 >> 10;
        int t0 = (m0 & 1023) + tr * 4;
        #pragma unroll
        for (int j = 0; j < 4; j++) {
            int gn = n0 + tc * 4 + j;
            float bz = bias[gn];
            float4 v;
            v.x = softplusf(acc[0][j] + bz);
            v.y = softplusf(acc[1][j] + bz);
            v.z = softplusf(acc[2][j] + bz);
            v.w = softplusf(acc[3][j] + bz);
            *(float4*)&g_dt_t[((size_t)bb * DI + gn) * L_ + t0] = v;
        }
    }
}

// =============================================================================
//  Fused chunked bidirectional scan (epilogue writes packed so (b,t,d))
// =============================================================================
__global__ __launch_bounds__(256)
void scan_fused(const float* __restrict__ A_log, const float* __restrict__ Dp)
{
    __shared__ float sP  [2][NS][CH];
    __shared__ float sS  [2][NS][CH];
    __shared__ float sCin[2][NS][CH];
    __shared__ float y0[L_];   // fwd contributions
    __shared__ float y1[L_];   // bwd contributions

    int bd   = blockIdx.x;
    int b    = bd >> 11;
    int d    = bd & (DI - 1);
    int c    = threadIdx.x >> 5;          // chunk
    int lane = threadIdx.x & 31;
    int n    = lane & 15;
    bool fw  = lane < 16;
    int dir  = fw ? 0 : 1;

    size_t off = ((size_t)b * DI + d) * L_;
    const float* dtp = g_dt_t  + off;
    const float* hp  = g_hid_t + off;
    const float* ssm = g_ssm   + (size_t)b * L_ * 96;
    float An = -__expf(A_log[d * NS + n]);

    int lo = c * CT, hi = lo + CT - 1;
    int sdelta = fw ? 96 : -96;

    // -------- phase A: chunk operator (P, S) --------
    {
        float s = 0.f, P = 1.f;
        float pb = (hi + 1 < L_) ? __expf(An * dtp[hi + 1]) : 0.f;
        const float* sp = ssm + (fw ? lo : hi) * 96 + 64 + n;
        for (int i0 = 0; i0 < CT; i0 += 4) {
            int tb = fw ? lo + i0 : hi - i0 - 3;
            float4 dt4 = *(const float4*)&dtp[tb];
            float4 h4  = *(const float4*)&hp[tb];
            float dts[4] = {dt4.x, dt4.y, dt4.z, dt4.w};
            float hs4[4] = {h4.x, h4.y, h4.z, h4.w};
            #pragma unroll
            for (int j = 0; j < 4; j++) {
                int jj = fw ? j : 3 - j;
                float dtv = dts[jj], h = hs4[jj];
                float a  = __expf(An * dtv);
                float Bv = sp[0];
                float u  = dtv * Bv * h;
                float coef = fw ? a : pb;
                s = fmaf(coef, s, u);
                P *= coef;
                pb = a;
                sp += sdelta;
            }
        }
        sP[dir][n][c] = P;
        sS[dir][n][c] = s;
    }
    __syncthreads();

    // -------- combine: 32 threads, one (dir, n) chain each --------
    if (threadIdx.x < 32) {
        int dr = threadIdx.x >> 4, nn = threadIdx.x & 15;
        float cin = 0.f;
        if (dr == 0) {
            #pragma unroll
            for (int cc = 0; cc < CH; cc++) {
                sCin[0][nn][cc] = cin;
                cin = fmaf(sP[0][nn][cc], cin, sS[0][nn][cc]);
            }
        } else {
            #pragma unroll
            for (int cc = CH - 1; cc >= 0; cc--) {
                sCin[1][nn][cc] = cin;
                cin = fmaf(sP[1][nn][cc], cin, sS[1][nn][cc]);
            }
        }
    }
    __syncthreads();

    // -------- phase C: seeded re-scan + multi-value shuffle reduction --------
    {
        float s  = sCin[dir][n][c];
        float pb = (hi + 1 < L_) ? __expf(An * dtp[hi + 1]) : 0.f;
        const float* sp = ssm + (fw ? lo : hi) * 96 + 64 + n;
        float* yarr = fw ? y0 : y1;
        int vsel = n >> 2;
        int psel = n & 3;
        for (int i0 = 0; i0 < CT; i0 += 4) {
            int tb = fw ? lo + i0 : hi - i0 - 3;
            float4 dt4 = *(const float4*)&dtp[tb];
            float4 h4  = *(const float4*)&hp[tb];
            float dts[4] = {dt4.x, dt4.y, dt4.z, dt4.w};
            float hs4[4] = {h4.x, h4.y, h4.z, h4.w};
            float v[4];
            #pragma unroll
            for (int j = 0; j < 4; j++) {
                int jj = fw ? j : 3 - j;
                float dtv = dts[jj], h = hs4[jj];
                float a  = __expf(An * dtv);
                float Bv = sp[0];
                float Cv = sp[16];
                float u  = dtv * Bv * h;
                float coef = fw ? a : pb;
                s = fmaf(coef, s, u);
                float base = fw ? s : (s - u);
                v[jj] = Cv * base;
                pb = a;
                sp += sdelta;
            }
            #pragma unroll
            for (int i = 0; i < 4; i++) {
                v[i] += __shfl_xor_sync(0xffffffffu, v[i], 8);
                v[i] += __shfl_xor_sync(0xffffffffu, v[i], 4);
            }
            float w = (vsel == 0) ? v[0] : (vsel == 1) ? v[1] : (vsel == 2) ? v[2] : v[3];
            w += __shfl_xor_sync(0xffffffffu, w, 2);
            w += __shfl_xor_sync(0xffffffffu, w, 1);
            if (psel == 0) yarr[tb + vsel] = w;
        }
    }
    __syncthreads();

    // -------- epilogue: gating -> packed bf16-split so, (b, t, d) ------------
    {
        float Dv = Dp[d];
        int t4 = threadIdx.x * 4;
        float4 g4 = *(const float4*)&g_gate_t[off + t4];
        float4 h4 = *(const float4*)&hp[t4];
        float4 ya = *(const float4*)&y0[t4];
        float4 yb = *(const float4*)&y1[t4];
        float o[4];
        o[0] = (1.3f * (ya.x + yb.x) + h4.x * Dv) * (g4.x / (1.f + __expf(-g4.x)));
        o[1] = (1.3f * (ya.y + yb.y) + h4.y * Dv) * (g4.y / (1.f + __expf(-g4.y)));
        o[2] = (1.3f * (ya.z + yb.z) + h4.z * Dv) * (g4.z / (1.f + __expf(-g4.z)));
        o[3] = (1.3f * (ya.w + yb.w) + h4.w * Dv) * (g4.w / (1.f + __expf(-g4.w)));
        u32* sop = g_so_pk + (size_t)b * L_ * DI + d;
        #pragma unroll
        for (int j = 0; j < 4; j++)
            sop[(size_t)(t4 + j) * DI] = pack_split(o[j]);
    }
}

// ---------------- launch -----------------------------------------------------
extern "C" void kernel_launch(void* const* d_in, const int* in_sizes, int n_in,
                              void* d_out, int out_size)
{
    const float* x      = (const float*)d_in[0];  // (2,1024,1024)
    const float* w_in   = (const float*)d_in[1];  // (4096,1024)
    const float* w_x    = (const float*)d_in[2];  // (96,2048)
    const float* w_dt   = (const float*)d_in[3];  // (2048,64)
    const float* b_dt   = (const float*)d_in[4];  // (2048,)
    const float* A_log  = (const float*)d_in[5];  // (2048,16)
    const float* Dvec   = (const float*)d_in[6];  // (2048,)
    const float* w_out  = (const float*)d_in[7];  // (1024,2048)
    float* out = (float*)d_out;                   // (2,1024,1024)

    const int M = BB * L_;  // 2048
    const int SM0 = 4 * (2 * 128 * 48 + 2 * 128 * 48);   // 98304
    const int SM1 = 4 * (2 * 128 * 48 + 2 * 64 * 48);    // 73728

    cudaFuncSetAttribute(gemm_mma<0>, cudaFuncAttributeMaxDynamicSharedMemorySize, SM0);
    cudaFuncSetAttribute(gemm_mma<1>, cudaFuncAttributeMaxDynamicSharedMemorySize, SM1);

    // 0) split inputs to bf16 hi/lo
    cvt_pack<0><<<(BB*L_*DM/4 + 255)/256, 256>>>(x,     BB*L_*DM/4);
    cvt_pack<1><<<(2*DI*DM/4  + 255)/256, 256>>>(w_in,  2*DI*DM/4);
    cvt_pack<2><<<(DM*DI/4    + 255)/256, 256>>>(w_out, DM*DI/4);

    // 1) in_proj (mma.sync bf16x3, 4-stage cp.async) -> hid/gate (b,d,t)
    gemm_mma<0><<<dim3(2*DI/128, M/128), 256, SM0>>>(DM, nullptr);
    // 2) x_proj: hidden (K-major) @ (96x2048)^T -> g_ssm
    gemm_k<1, true, 1><<<dim3(2, M/64), 256>>>(w_x, M, 96, DI, 0, nullptr);
    // 3) dt_proj: ssm[:, :64] @ (2048x64)^T + b, softplus -> g_dt_t
    gemm_k<2, false, 2><<<dim3(DI/64, M/64), 256>>>(w_dt, M, DI, DR, 96, b_dt);
    // 4) fused chunked bidirectional scan (writes packed so)
    scan_fused<<<BB * DI, 256>>>(A_log, Dvec);
    // 4b) split so into hi/lo (coalesced)
    cvt_so<<<(BB*L_*DI/4 + 255)/256, 256>>>(BB*L_*DI/4);
    // 5) out_proj (mma.sync bf16x3, tile 128x64 -> 256 CTAs)
    gemm_mma<1><<<dim3(DM/64, M/128), 256, SM1>>>(DI, out);
}